// round 15
// baseline (speedup 1.0000x reference)
#include <cuda_runtime.h>
#include <cuda_fp16.h>
#include <stdint.h>

// RGINConv: out = feat + segment_sum_dst( feat[src] @ W[etype] )
//
// Order: CSR build -> W transpose -> GEMM (per-rel grid, R11 form) -> pull.
//   - scan1 self-cleans g_deg (no zero kernel; graph-replay invariant).
//   - hist/scatter vectorized 4 edges/thread.
//   - Y fp16 (102MB), fp16 mma m16n8k16 w/ fp32 accum.

#define DFEAT 128
#define MAX_N 50048
#define MAX_E 640000
#define MAX_R 8
#define SCAN_CHUNK 1024
#define MAX_NB ((MAX_N + SCAN_CHUNK - 1) / SCAN_CHUNK)

__device__ __half    g_Y[(size_t)MAX_R * MAX_N * DFEAT];  // ~102 MB scratch
__device__ __half    g_Wt[MAX_R * DFEAT * DFEAT];         // W transposed, fp16
__device__ int       g_rowptr[MAX_N + 1];
__device__ int       g_cursor[MAX_N];
__device__ int       g_deg[MAX_N];                        // zero at every launch
__device__ int       g_bsum[MAX_NB];
__device__ unsigned  g_elist[MAX_E];   // half-offset of Y row for this edge

// ---------------------------------------------------------------------------
// hist: 4 edges per thread via int4.
// ---------------------------------------------------------------------------
__global__ void hist_k(const int* __restrict__ dst, int E)
{
    int q  = blockIdx.x * blockDim.x + threadIdx.x;
    int e0 = q * 4;
    if (e0 + 3 < E) {
        int4 d = *(const int4*)(dst + e0);
        atomicAdd(&g_deg[d.x], 1);
        atomicAdd(&g_deg[d.y], 1);
        atomicAdd(&g_deg[d.z], 1);
        atomicAdd(&g_deg[d.w], 1);
    } else {
        for (int e = e0; e < E; ++e) atomicAdd(&g_deg[dst[e]], 1);
    }
}

// ---------------------------------------------------------------------------
// Scan stage 1: block-local scan of 1024 degrees; also re-zeroes g_deg so the
// next graph replay starts from a clean histogram.
// ---------------------------------------------------------------------------
__global__ void scan1_k(int n)
{
    const int tid  = threadIdx.x;
    const int blk  = blockIdx.x;
    const int base = blk * SCAN_CHUNK + tid * 4;

    int d0 = 0, d1 = 0, d2 = 0, d3 = 0;
    if (base     < n) { d0 = g_deg[base];     g_deg[base]     = 0; }
    if (base + 1 < n) { d1 = g_deg[base + 1]; g_deg[base + 1] = 0; }
    if (base + 2 < n) { d2 = g_deg[base + 2]; g_deg[base + 2] = 0; }
    if (base + 3 < n) { d3 = g_deg[base + 3]; g_deg[base + 3] = 0; }
    int s = d0 + d1 + d2 + d3;

    const int lane = tid & 31, wid = tid >> 5;
    int v = s;
#pragma unroll
    for (int off = 1; off < 32; off <<= 1) {
        int t = __shfl_up_sync(0xffffffffu, v, off);
        if (lane >= off) v += t;
    }
    __shared__ int ws[8];
    if (lane == 31) ws[wid] = v;
    __syncthreads();
    if (tid == 0) {
        int r = 0;
#pragma unroll
        for (int i = 0; i < 8; ++i) { int t = ws[i]; ws[i] = r; r += t; }
    }
    __syncthreads();

    int excl = (v - s) + ws[wid];
    if (tid == 255) g_bsum[blk] = excl + s;

    if (base     < n) g_rowptr[base]     = excl;           excl += d0;
    if (base + 1 < n) g_rowptr[base + 1] = excl;           excl += d1;
    if (base + 2 < n) g_rowptr[base + 2] = excl;           excl += d2;
    if (base + 3 < n) g_rowptr[base + 3] = excl;
}

__global__ void scan2_k(int nb)
{
    const int lane = threadIdx.x;
    int i0 = lane * 2, i1 = lane * 2 + 1;
    int a = (i0 < nb) ? g_bsum[i0] : 0;
    int b = (i1 < nb) ? g_bsum[i1] : 0;
    int s = a + b, v = s;
#pragma unroll
    for (int off = 1; off < 32; off <<= 1) {
        int t = __shfl_up_sync(0xffffffffu, v, off);
        if (lane >= off) v += t;
    }
    int excl = v - s;
    if (i0 < nb) g_bsum[i0] = excl;
    if (i1 < nb) g_bsum[i1] = excl + a;
}

__global__ void scan3_k(int n, int E)
{
    const int tid  = threadIdx.x;
    const int blk  = blockIdx.x;
    const int off  = g_bsum[blk];
    const int base = blk * SCAN_CHUNK + tid * 4;
#pragma unroll
    for (int j = 0; j < 4; ++j) {
        int idx = base + j;
        if (idx < n) {
            int r = g_rowptr[idx] + off;
            g_rowptr[idx] = r;
            g_cursor[idx] = r;
        }
    }
    if (blk == 0 && tid == 0) g_rowptr[n] = E;
}

// ---------------------------------------------------------------------------
// scatter: 4 edges per thread via int4.
// ---------------------------------------------------------------------------
__global__ void scatter_k(const int* __restrict__ src, const int* __restrict__ dst,
                          const int* __restrict__ et, int E, int n)
{
    int q  = blockIdx.x * blockDim.x + threadIdx.x;
    int e0 = q * 4;
    if (e0 + 3 < E) {
        int4 d = *(const int4*)(dst + e0);
        int4 s = *(const int4*)(src + e0);
        int4 t = *(const int4*)(et  + e0);
        int p0 = atomicAdd(&g_cursor[d.x], 1);
        int p1 = atomicAdd(&g_cursor[d.y], 1);
        int p2 = atomicAdd(&g_cursor[d.z], 1);
        int p3 = atomicAdd(&g_cursor[d.w], 1);
        g_elist[p0] = ((unsigned)t.x * (unsigned)n + (unsigned)s.x) * (unsigned)DFEAT;
        g_elist[p1] = ((unsigned)t.y * (unsigned)n + (unsigned)s.y) * (unsigned)DFEAT;
        g_elist[p2] = ((unsigned)t.z * (unsigned)n + (unsigned)s.z) * (unsigned)DFEAT;
        g_elist[p3] = ((unsigned)t.w * (unsigned)n + (unsigned)s.w) * (unsigned)DFEAT;
    } else {
        for (int e = e0; e < E; ++e) {
            int p = atomicAdd(&g_cursor[dst[e]], 1);
            g_elist[p] = ((unsigned)et[e] * (unsigned)n + (unsigned)src[e]) * (unsigned)DFEAT;
        }
    }
}

// ---------------------------------------------------------------------------
// W transpose: Wt[r][n][k] = (half)W[r][k][n].  grid (4,4,R), block (32,8).
// ---------------------------------------------------------------------------
__global__ void transpose_w(const float* __restrict__ W)
{
    __shared__ float t[32][33];
    const int r  = blockIdx.z;
    const int k0 = blockIdx.x * 32;
    const int n0 = blockIdx.y * 32;
    const float* Wr = W + (size_t)r * DFEAT * DFEAT;
#pragma unroll
    for (int j = 0; j < 4; ++j)
        t[threadIdx.y + j * 8][threadIdx.x] =
            Wr[(size_t)(k0 + threadIdx.y + j * 8) * DFEAT + n0 + threadIdx.x];
    __syncthreads();
    __half* Wt = g_Wt + (size_t)r * DFEAT * DFEAT;
#pragma unroll
    for (int j = 0; j < 4; ++j)
        Wt[(size_t)(n0 + threadIdx.y + j * 8) * DFEAT + k0 + threadIdx.x] =
            __float2half(t[threadIdx.x][threadIdx.y + j * 8]);
}

// ---------------------------------------------------------------------------
// GEMM (R11 form): grid (n/64, R). Y[rel] = feat @ W[rel].
// CTA tile: 64(M) x 128(N); 8 warps 2x4, warp tile 32x32.
// fp16 mma m16n8k16, fp32 accum, fp16 store. Smem LD=136 halves.
// ---------------------------------------------------------------------------
#define TM 64
#define HLD 136

__global__ void __launch_bounds__(256, 2)
gemm_feat_w(const float* __restrict__ feat, int n_nodes)
{
    extern __shared__ __half sh[];
    __half* As = sh;                 // [TM][HLD]
    __half* Bs = sh + TM * HLD;      // [128][HLD]

    const int rel  = blockIdx.y;
    const int row0 = blockIdx.x * TM;
    const int tid  = threadIdx.x;

#pragma unroll
    for (int it = 0; it < (TM * DFEAT) / (256 * 4); ++it) {
        int idx = it * 256 + tid;
        int r   = idx >> 5;
        int c   = (idx & 31) * 4;
        float4 v = make_float4(0.f, 0.f, 0.f, 0.f);
        int gr = row0 + r;
        if (gr < n_nodes) v = *(const float4*)(feat + (size_t)gr * DFEAT + c);
        __half2* p = (__half2*)(As + r * HLD + c);
        p[0] = __floats2half2_rn(v.x, v.y);
        p[1] = __floats2half2_rn(v.z, v.w);
    }
    const float4* Wt4 = (const float4*)(g_Wt + (size_t)rel * DFEAT * DFEAT);
#pragma unroll
    for (int it = 0; it < (DFEAT * DFEAT) / (256 * 8); ++it) {
        int idx  = it * 256 + tid;      // 16-byte chunk index (8 halves)
        int nrow = idx >> 4;
        int koff = (idx & 15) * 8;
        *(float4*)(Bs + nrow * HLD + koff) = Wt4[idx];
    }
    __syncthreads();

    const int wid  = tid >> 5;
    const int lane = tid & 31;
    const int g    = lane >> 2;
    const int c    = lane & 3;
    const int wm   = wid & 1;
    const int wn   = wid >> 1;

    float acc[2][4][4];
#pragma unroll
    for (int mt = 0; mt < 2; ++mt)
#pragma unroll
        for (int nt = 0; nt < 4; ++nt)
#pragma unroll
            for (int i = 0; i < 4; ++i) acc[mt][nt][i] = 0.f;

#pragma unroll
    for (int k0 = 0; k0 < DFEAT; k0 += 16) {
        unsigned a[2][4], b[4][2];
#pragma unroll
        for (int mt = 0; mt < 2; ++mt) {
            int rb = wm * 32 + mt * 16;
            a[mt][0] = *(const unsigned*)(As + (rb + g)     * HLD + k0 + 2 * c);
            a[mt][1] = *(const unsigned*)(As + (rb + g + 8) * HLD + k0 + 2 * c);
            a[mt][2] = *(const unsigned*)(As + (rb + g)     * HLD + k0 + 2 * c + 8);
            a[mt][3] = *(const unsigned*)(As + (rb + g + 8) * HLD + k0 + 2 * c + 8);
        }
#pragma unroll
        for (int nt = 0; nt < 4; ++nt) {
            int nb = wn * 32 + nt * 8;
            b[nt][0] = *(const unsigned*)(Bs + (nb + g) * HLD + k0 + 2 * c);
            b[nt][1] = *(const unsigned*)(Bs + (nb + g) * HLD + k0 + 2 * c + 8);
        }
#pragma unroll
        for (int mt = 0; mt < 2; ++mt)
#pragma unroll
            for (int nt = 0; nt < 4; ++nt)
                asm volatile(
                    "mma.sync.aligned.m16n8k16.row.col.f32.f16.f16.f32 "
                    "{%0,%1,%2,%3}, {%4,%5,%6,%7}, {%8,%9}, {%0,%1,%2,%3};"
                    : "+f"(acc[mt][nt][0]), "+f"(acc[mt][nt][1]),
                      "+f"(acc[mt][nt][2]), "+f"(acc[mt][nt][3])
                    : "r"(a[mt][0]), "r"(a[mt][1]), "r"(a[mt][2]), "r"(a[mt][3]),
                      "r"(b[nt][0]), "r"(b[nt][1]));
    }

    __half* Yr = g_Y + (size_t)rel * n_nodes * DFEAT;
#pragma unroll
    for (int mt = 0; mt < 2; ++mt) {
        int r_lo = row0 + wm * 32 + mt * 16 + g;
        int r_hi = r_lo + 8;
#pragma unroll
        for (int nt = 0; nt < 4; ++nt) {
            int col = wn * 32 + nt * 8 + 2 * c;
            if (r_lo < n_nodes)
                *(__half2*)(Yr + (size_t)r_lo * DFEAT + col) =
                    __floats2half2_rn(acc[mt][nt][0], acc[mt][nt][1]);
            if (r_hi < n_nodes)
                *(__half2*)(Yr + (size_t)r_hi * DFEAT + col) =
                    __floats2half2_rn(acc[mt][nt][2], acc[mt][nt][3]);
        }
    }
}

// ---------------------------------------------------------------------------
// Pull: one warp per node. acc(fp32) = feat[n] + sum of fp16 Y rows.
// ---------------------------------------------------------------------------
__device__ __forceinline__ void acc_half4(float4& acc, uint2 u)
{
    float2 f0 = __half22float2(*(__half2*)&u.x);
    float2 f1 = __half22float2(*(__half2*)&u.y);
    acc.x += f0.x; acc.y += f0.y; acc.z += f1.x; acc.w += f1.y;
}

__global__ void __launch_bounds__(256)
pull_k(const float* __restrict__ feat, float* __restrict__ out, int n)
{
    int gw   = (blockIdx.x * 256 + threadIdx.x) >> 5;
    int lane = threadIdx.x & 31;
    if (gw >= n) return;

    int s = g_rowptr[gw];
    int e = g_rowptr[gw + 1];

    float4 acc = *((const float4*)feat + (size_t)gw * 32 + lane);
    const unsigned lo = (unsigned)lane * 4;

    int i = s;
    for (; i + 8 <= e; i += 8) {
        uint2 u[8];
#pragma unroll
        for (int j = 0; j < 8; ++j) {
            unsigned o = g_elist[i + j];
            u[j] = *(const uint2*)(g_Y + (size_t)o + lo);
        }
#pragma unroll
        for (int j = 0; j < 8; ++j) acc_half4(acc, u[j]);
    }
    for (; i + 2 <= e; i += 2) {
        unsigned o0 = g_elist[i];
        unsigned o1 = g_elist[i + 1];
        uint2 u0 = *(const uint2*)(g_Y + (size_t)o0 + lo);
        uint2 u1 = *(const uint2*)(g_Y + (size_t)o1 + lo);
        acc_half4(acc, u0);
        acc_half4(acc, u1);
    }
    if (i < e) {
        unsigned o = g_elist[i];
        uint2 u = *(const uint2*)(g_Y + (size_t)o + lo);
        acc_half4(acc, u);
    }

    *((float4*)out + (size_t)gw * 32 + lane) = acc;
}

// ---------------------------------------------------------------------------
// Launch: CSR first, GEMM right before pull (keeps Y tail in L2 for pull).
// ---------------------------------------------------------------------------
extern "C" void kernel_launch(void* const* d_in, const int* in_sizes, int n_in,
                              void* d_out, int out_size)
{
    const float* feat = (const float*)d_in[0];
    const float* W    = (const float*)d_in[1];
    const int*   et   = (const int*)d_in[2];
    const int*   src  = (const int*)d_in[3];
    const int*   dst  = (const int*)d_in[4];
    float*       out  = (float*)d_out;

    const int n  = in_sizes[0] / DFEAT;                 // 50000
    const int R  = in_sizes[1] / (DFEAT * DFEAT);       // 8
    const int E  = in_sizes[2];                          // 640000
    const int nb = (n + SCAN_CHUNK - 1) / SCAN_CHUNK;    // 49
    const int eq = (E + 3) / 4;                          // 4 edges per thread

    hist_k   <<<(eq + 255) / 256, 256>>>(dst, E);
    scan1_k  <<<nb, 256>>>(n);
    scan2_k  <<<1, 32>>>(nb);
    scan3_k  <<<nb, 256>>>(n, E);
    scatter_k<<<(eq + 255) / 256, 256>>>(src, dst, et, E, n);

    dim3 tg(DFEAT / 32, DFEAT / 32, R);
    transpose_w<<<tg, dim3(32, 8)>>>(W);

    const int smem_bytes = (TM * HLD + DFEAT * HLD) * 2;  // ~52 KB
    cudaFuncSetAttribute(gemm_feat_w,
                         cudaFuncAttributeMaxDynamicSharedMemorySize, smem_bytes);
    dim3 gg((n + TM - 1) / TM, R);
    gemm_feat_w<<<gg, 256, smem_bytes>>>(feat, n);

    pull_k<<<(n * 32 + 255) / 256, 256>>>(feat, out, n);
}

// round 16
// speedup vs baseline: 1.4078x; 1.4078x over previous
#include <cuda_runtime.h>
#include <cuda_fp16.h>
#include <stdint.h>

// RGINConv: out = feat + segment_sum_dst( feat[src] @ W[etype] )
//
// R11 configuration (measured best, 131.5us) with exactly one delta:
//   - zero_deg_k removed; scan1_k self-cleans g_deg (replay-safe).
//   - launch order arranged so the GEMM is the 4th launch (ncu -s5 -c1
//     captures launch #4 -> next round profiles the GEMM).
//   1. Y[r] = feat @ W[r]  (fp16 mma m16n8k16, fp32 accum, fp16 store)
//   2. CSR of edges grouped by dst (hist + hierarchical scan + scatter)
//   3. Pull: warp per node, acc(fp32) = feat[n] + sum of fp16 Y rows

#define DFEAT 128
#define MAX_N 50048
#define MAX_E 640000
#define MAX_R 8
#define SCAN_CHUNK 1024
#define MAX_NB ((MAX_N + SCAN_CHUNK - 1) / SCAN_CHUNK)

__device__ __half    g_Y[(size_t)MAX_R * MAX_N * DFEAT];  // ~102 MB scratch
__device__ __half    g_Wt[MAX_R * DFEAT * DFEAT];         // W transposed, fp16
__device__ int       g_rowptr[MAX_N + 1];
__device__ int       g_cursor[MAX_N];
__device__ int       g_deg[MAX_N];                        // zero at every launch
__device__ int       g_bsum[MAX_NB];
__device__ unsigned  g_elist[MAX_E];   // half-offset of Y row for this edge

// ---------------------------------------------------------------------------
// W transpose: Wt[r][n][k] = (half)W[r][k][n].  grid (4,4,R), block (32,8).
// ---------------------------------------------------------------------------
__global__ void transpose_w(const float* __restrict__ W)
{
    __shared__ float t[32][33];
    const int r  = blockIdx.z;
    const int k0 = blockIdx.x * 32;
    const int n0 = blockIdx.y * 32;
    const float* Wr = W + (size_t)r * DFEAT * DFEAT;
#pragma unroll
    for (int j = 0; j < 4; ++j)
        t[threadIdx.y + j * 8][threadIdx.x] =
            Wr[(size_t)(k0 + threadIdx.y + j * 8) * DFEAT + n0 + threadIdx.x];
    __syncthreads();
    __half* Wt = g_Wt + (size_t)r * DFEAT * DFEAT;
#pragma unroll
    for (int j = 0; j < 4; ++j)
        Wt[(size_t)(n0 + threadIdx.y + j * 8) * DFEAT + k0 + threadIdx.x] =
            __float2half(t[threadIdx.x][threadIdx.y + j * 8]);
}

// ---------------------------------------------------------------------------
// GEMM: grid (n/64, R). Y[rel] = feat @ W[rel].
// CTA tile: 64(M) x 128(N); 8 warps 2x4, warp tile 32x32.
// fp16 mma m16n8k16, fp32 accum, fp16 store. Smem LD=136 halves.
// ---------------------------------------------------------------------------
#define TM 64
#define HLD 136

__global__ void __launch_bounds__(256, 2)
gemm_feat_w(const float* __restrict__ feat, int n_nodes)
{
    extern __shared__ __half sh[];
    __half* As = sh;                 // [TM][HLD]
    __half* Bs = sh + TM * HLD;      // [128][HLD]

    const int rel  = blockIdx.y;
    const int row0 = blockIdx.x * TM;
    const int tid  = threadIdx.x;

#pragma unroll
    for (int it = 0; it < (TM * DFEAT) / (256 * 4); ++it) {
        int idx = it * 256 + tid;
        int r   = idx >> 5;
        int c   = (idx & 31) * 4;
        float4 v = make_float4(0.f, 0.f, 0.f, 0.f);
        int gr = row0 + r;
        if (gr < n_nodes) v = *(const float4*)(feat + (size_t)gr * DFEAT + c);
        __half2* p = (__half2*)(As + r * HLD + c);
        p[0] = __floats2half2_rn(v.x, v.y);
        p[1] = __floats2half2_rn(v.z, v.w);
    }
    const float4* Wt4 = (const float4*)(g_Wt + (size_t)rel * DFEAT * DFEAT);
#pragma unroll
    for (int it = 0; it < (DFEAT * DFEAT) / (256 * 8); ++it) {
        int idx  = it * 256 + tid;      // 16-byte chunk index (8 halves)
        int nrow = idx >> 4;
        int koff = (idx & 15) * 8;
        *(float4*)(Bs + nrow * HLD + koff) = Wt4[idx];
    }
    __syncthreads();

    const int wid  = tid >> 5;
    const int lane = tid & 31;
    const int g    = lane >> 2;
    const int c    = lane & 3;
    const int wm   = wid & 1;
    const int wn   = wid >> 1;

    float acc[2][4][4];
#pragma unroll
    for (int mt = 0; mt < 2; ++mt)
#pragma unroll
        for (int nt = 0; nt < 4; ++nt)
#pragma unroll
            for (int i = 0; i < 4; ++i) acc[mt][nt][i] = 0.f;

#pragma unroll
    for (int k0 = 0; k0 < DFEAT; k0 += 16) {
        unsigned a[2][4], b[4][2];
#pragma unroll
        for (int mt = 0; mt < 2; ++mt) {
            int rb = wm * 32 + mt * 16;
            a[mt][0] = *(const unsigned*)(As + (rb + g)     * HLD + k0 + 2 * c);
            a[mt][1] = *(const unsigned*)(As + (rb + g + 8) * HLD + k0 + 2 * c);
            a[mt][2] = *(const unsigned*)(As + (rb + g)     * HLD + k0 + 2 * c + 8);
            a[mt][3] = *(const unsigned*)(As + (rb + g + 8) * HLD + k0 + 2 * c + 8);
        }
#pragma unroll
        for (int nt = 0; nt < 4; ++nt) {
            int nb = wn * 32 + nt * 8;
            b[nt][0] = *(const unsigned*)(Bs + (nb + g) * HLD + k0 + 2 * c);
            b[nt][1] = *(const unsigned*)(Bs + (nb + g) * HLD + k0 + 2 * c + 8);
        }
#pragma unroll
        for (int mt = 0; mt < 2; ++mt)
#pragma unroll
            for (int nt = 0; nt < 4; ++nt)
                asm volatile(
                    "mma.sync.aligned.m16n8k16.row.col.f32.f16.f16.f32 "
                    "{%0,%1,%2,%3}, {%4,%5,%6,%7}, {%8,%9}, {%0,%1,%2,%3};"
                    : "+f"(acc[mt][nt][0]), "+f"(acc[mt][nt][1]),
                      "+f"(acc[mt][nt][2]), "+f"(acc[mt][nt][3])
                    : "r"(a[mt][0]), "r"(a[mt][1]), "r"(a[mt][2]), "r"(a[mt][3]),
                      "r"(b[nt][0]), "r"(b[nt][1]));
    }

    __half* Yr = g_Y + (size_t)rel * n_nodes * DFEAT;
#pragma unroll
    for (int mt = 0; mt < 2; ++mt) {
        int r_lo = row0 + wm * 32 + mt * 16 + g;
        int r_hi = r_lo + 8;
#pragma unroll
        for (int nt = 0; nt < 4; ++nt) {
            int col = wn * 32 + nt * 8 + 2 * c;
            if (r_lo < n_nodes)
                *(__half2*)(Yr + (size_t)r_lo * DFEAT + col) =
                    __floats2half2_rn(acc[mt][nt][0], acc[mt][nt][1]);
            if (r_hi < n_nodes)
                *(__half2*)(Yr + (size_t)r_hi * DFEAT + col) =
                    __floats2half2_rn(acc[mt][nt][2], acc[mt][nt][3]);
        }
    }
}

// ---------------------------------------------------------------------------
// CSR build (R11 scalar forms)
// ---------------------------------------------------------------------------
__global__ void hist_k(const int* __restrict__ dst, int E)
{
    int e = blockIdx.x * blockDim.x + threadIdx.x;
    if (e < E) atomicAdd(&g_deg[dst[e]], 1);
}

// scan1 consumes AND re-zeroes g_deg (replay-safe; replaces zero_deg_k).
__global__ void scan1_k(int n)
{
    const int tid  = threadIdx.x;
    const int blk  = blockIdx.x;
    const int base = blk * SCAN_CHUNK + tid * 4;

    int d0 = 0, d1 = 0, d2 = 0, d3 = 0;
    if (base     < n) { d0 = g_deg[base];     g_deg[base]     = 0; }
    if (base + 1 < n) { d1 = g_deg[base + 1]; g_deg[base + 1] = 0; }
    if (base + 2 < n) { d2 = g_deg[base + 2]; g_deg[base + 2] = 0; }
    if (base + 3 < n) { d3 = g_deg[base + 3]; g_deg[base + 3] = 0; }
    int s = d0 + d1 + d2 + d3;

    const int lane = tid & 31, wid = tid >> 5;
    int v = s;
#pragma unroll
    for (int off = 1; off < 32; off <<= 1) {
        int t = __shfl_up_sync(0xffffffffu, v, off);
        if (lane >= off) v += t;
    }
    __shared__ int ws[8];
    if (lane == 31) ws[wid] = v;
    __syncthreads();
    if (tid == 0) {
        int r = 0;
#pragma unroll
        for (int i = 0; i < 8; ++i) { int t = ws[i]; ws[i] = r; r += t; }
    }
    __syncthreads();

    int excl = (v - s) + ws[wid];
    if (tid == 255) g_bsum[blk] = excl + s;

    if (base     < n) g_rowptr[base]     = excl;           excl += d0;
    if (base + 1 < n) g_rowptr[base + 1] = excl;           excl += d1;
    if (base + 2 < n) g_rowptr[base + 2] = excl;           excl += d2;
    if (base + 3 < n) g_rowptr[base + 3] = excl;
}

__global__ void scan2_k(int nb)
{
    const int lane = threadIdx.x;
    int i0 = lane * 2, i1 = lane * 2 + 1;
    int a = (i0 < nb) ? g_bsum[i0] : 0;
    int b = (i1 < nb) ? g_bsum[i1] : 0;
    int s = a + b, v = s;
#pragma unroll
    for (int off = 1; off < 32; off <<= 1) {
        int t = __shfl_up_sync(0xffffffffu, v, off);
        if (lane >= off) v += t;
    }
    int excl = v - s;
    if (i0 < nb) g_bsum[i0] = excl;
    if (i1 < nb) g_bsum[i1] = excl + a;
}

__global__ void scan3_k(int n, int E)
{
    const int tid  = threadIdx.x;
    const int blk  = blockIdx.x;
    const int off  = g_bsum[blk];
    const int base = blk * SCAN_CHUNK + tid * 4;
#pragma unroll
    for (int j = 0; j < 4; ++j) {
        int idx = base + j;
        if (idx < n) {
            int r = g_rowptr[idx] + off;
            g_rowptr[idx] = r;
            g_cursor[idx] = r;
        }
    }
    if (blk == 0 && tid == 0) g_rowptr[n] = E;
}

__global__ void scatter_k(const int* __restrict__ src, const int* __restrict__ dst,
                          const int* __restrict__ et, int E, int n)
{
    int e = blockIdx.x * blockDim.x + threadIdx.x;
    if (e >= E) return;
    int d   = dst[e];
    int pos = atomicAdd(&g_cursor[d], 1);
    g_elist[pos] = ((unsigned)et[e] * (unsigned)n + (unsigned)src[e]) * (unsigned)DFEAT;
}

// ---------------------------------------------------------------------------
// Pull: one warp per node. acc(fp32) = feat[n] + sum of fp16 Y rows.
// ---------------------------------------------------------------------------
__device__ __forceinline__ void acc_half4(float4& acc, uint2 u)
{
    float2 f0 = __half22float2(*(__half2*)&u.x);
    float2 f1 = __half22float2(*(__half2*)&u.y);
    acc.x += f0.x; acc.y += f0.y; acc.z += f1.x; acc.w += f1.y;
}

__global__ void __launch_bounds__(256)
pull_k(const float* __restrict__ feat, float* __restrict__ out, int n)
{
    int gw   = (blockIdx.x * 256 + threadIdx.x) >> 5;
    int lane = threadIdx.x & 31;
    if (gw >= n) return;

    int s = g_rowptr[gw];
    int e = g_rowptr[gw + 1];

    float4 acc = *((const float4*)feat + (size_t)gw * 32 + lane);
    const unsigned lo = (unsigned)lane * 4;

    int i = s;
    for (; i + 8 <= e; i += 8) {
        uint2 u[8];
#pragma unroll
        for (int j = 0; j < 8; ++j) {
            unsigned o = g_elist[i + j];
            u[j] = *(const uint2*)(g_Y + (size_t)o + lo);
        }
#pragma unroll
        for (int j = 0; j < 8; ++j) acc_half4(acc, u[j]);
    }
    for (; i + 2 <= e; i += 2) {
        unsigned o0 = g_elist[i];
        unsigned o1 = g_elist[i + 1];
        uint2 u0 = *(const uint2*)(g_Y + (size_t)o0 + lo);
        uint2 u1 = *(const uint2*)(g_Y + (size_t)o1 + lo);
        acc_half4(acc, u0);
        acc_half4(acc, u1);
    }
    if (i < e) {
        unsigned o = g_elist[i];
        uint2 u = *(const uint2*)(g_Y + (size_t)o + lo);
        acc_half4(acc, u);
    }

    *((float4*)out + (size_t)gw * 32 + lane) = acc;
}

// ---------------------------------------------------------------------------
// Launch. Order chosen so gemm_feat_w is the 4TH launch (ncu captures #4):
//   hist -> transpose -> scan1 -> GEMM -> scan2 -> scan3 -> scatter -> pull
// (all dependencies respected: scan1 after hist; gemm after transpose;
//  scatter after scan3; pull after gemm+scatter)
// ---------------------------------------------------------------------------
extern "C" void kernel_launch(void* const* d_in, const int* in_sizes, int n_in,
                              void* d_out, int out_size)
{
    const float* feat = (const float*)d_in[0];
    const float* W    = (const float*)d_in[1];
    const int*   et   = (const int*)d_in[2];
    const int*   src  = (const int*)d_in[3];
    const int*   dst  = (const int*)d_in[4];
    float*       out  = (float*)d_out;

    const int n  = in_sizes[0] / DFEAT;                 // 50000
    const int R  = in_sizes[1] / (DFEAT * DFEAT);       // 8
    const int E  = in_sizes[2];                          // 640000
    const int nb = (n + SCAN_CHUNK - 1) / SCAN_CHUNK;    // 49

    const int smem_bytes = (TM * HLD + DFEAT * HLD) * 2;  // ~52 KB
    cudaFuncSetAttribute(gemm_feat_w,
                         cudaFuncAttributeMaxDynamicSharedMemorySize, smem_bytes);

    dim3 tg(DFEAT / 32, DFEAT / 32, R);
    dim3 gg((n + TM - 1) / TM, R);

    hist_k     <<<(E + 255) / 256, 256>>>(dst, E);       // 1
    transpose_w<<<tg, dim3(32, 8)>>>(W);                 // 2
    scan1_k    <<<nb, 256>>>(n);                         // 3
    gemm_feat_w<<<gg, 256, smem_bytes>>>(feat, n);       // 4  <- ncu capture
    scan2_k    <<<1, 32>>>(nb);                          // 5
    scan3_k    <<<nb, 256>>>(n, E);                      // 6
    scatter_k  <<<(E + 255) / 256, 256>>>(src, dst, et, E, n);  // 7
    pull_k     <<<(n * 32 + 255) / 256, 256>>>(feat, out, n);   // 8
}

// round 17
// speedup vs baseline: 1.5266x; 1.0844x over previous
#include <cuda_runtime.h>
#include <cuda_fp16.h>
#include <stdint.h>

// RGINConv: out = feat + segment_sum_dst( feat[src] @ W[etype] )
//
// Delta vs R16 (131.5us): GEMM rewritten -- CTA tile 128x128, warp tile 32x64,
// fragments via ldmatrix.x4 (was 16 scalar LDS per 8 mma; now 6 LDSM per 16).
// ncu R16 showed gemm: L1=82%, tensor=28% -> smem-instruction bound.

#define DFEAT 128
#define MAX_N 50048
#define MAX_E 640000
#define MAX_R 8
#define SCAN_CHUNK 1024
#define MAX_NB ((MAX_N + SCAN_CHUNK - 1) / SCAN_CHUNK)

__device__ __half    g_Y[(size_t)MAX_R * MAX_N * DFEAT];  // ~102 MB scratch
__device__ __half    g_Wt[MAX_R * DFEAT * DFEAT];         // W transposed, fp16
__device__ int       g_rowptr[MAX_N + 1];
__device__ int       g_cursor[MAX_N];
__device__ int       g_deg[MAX_N];                        // zero at every launch
__device__ int       g_bsum[MAX_NB];
__device__ unsigned  g_elist[MAX_E];   // half-offset of Y row for this edge

// ---------------------------------------------------------------------------
// W transpose: Wt[r][n][k] = (half)W[r][k][n].  grid (4,4,R), block (32,8).
// ---------------------------------------------------------------------------
__global__ void transpose_w(const float* __restrict__ W)
{
    __shared__ float t[32][33];
    const int r  = blockIdx.z;
    const int k0 = blockIdx.x * 32;
    const int n0 = blockIdx.y * 32;
    const float* Wr = W + (size_t)r * DFEAT * DFEAT;
#pragma unroll
    for (int j = 0; j < 4; ++j)
        t[threadIdx.y + j * 8][threadIdx.x] =
            Wr[(size_t)(k0 + threadIdx.y + j * 8) * DFEAT + n0 + threadIdx.x];
    __syncthreads();
    __half* Wt = g_Wt + (size_t)r * DFEAT * DFEAT;
#pragma unroll
    for (int j = 0; j < 4; ++j)
        Wt[(size_t)(n0 + threadIdx.y + j * 8) * DFEAT + k0 + threadIdx.x] =
            __float2half(t[threadIdx.x][threadIdx.y + j * 8]);
}

// ---------------------------------------------------------------------------
// GEMM: grid (n/128, R). Y[rel] = feat @ W[rel].
// CTA tile 128(M) x 128(N); 8 warps 4(M) x 2(N); warp tile 32 x 64.
// Fragments via ldmatrix.x4; fp16 mma m16n8k16, fp32 accum, fp16 store.
// Smem rows HLD=136 halves (272B) -> ldmatrix rows 4 banks apart: conflict-free.
// ---------------------------------------------------------------------------
#define TM 128
#define HLD 136

__device__ __forceinline__ void ldsm_x4(unsigned& r0, unsigned& r1,
                                        unsigned& r2, unsigned& r3, unsigned addr)
{
    asm volatile("ldmatrix.sync.aligned.m8n8.x4.shared.b16 {%0,%1,%2,%3}, [%4];"
                 : "=r"(r0), "=r"(r1), "=r"(r2), "=r"(r3) : "r"(addr));
}

__global__ void __launch_bounds__(256, 2)
gemm_feat_w(const float* __restrict__ feat, int n_nodes)
{
    extern __shared__ __half sh[];
    __half* As = sh;                 // [128][HLD]
    __half* Bs = sh + TM * HLD;      // [128][HLD]

    const int rel  = blockIdx.y;
    const int row0 = blockIdx.x * TM;
    const int tid  = threadIdx.x;

    // A tile: 128x128 floats -> fp16. 16 float4 per thread.
#pragma unroll
    for (int it = 0; it < (TM * DFEAT) / (256 * 4); ++it) {
        int idx = it * 256 + tid;
        int r   = idx >> 5;
        int c   = (idx & 31) * 4;
        float4 v = make_float4(0.f, 0.f, 0.f, 0.f);
        int gr = row0 + r;
        if (gr < n_nodes) v = *(const float4*)(feat + (size_t)gr * DFEAT + c);
        __half2* p = (__half2*)(As + r * HLD + c);
        p[0] = __floats2half2_rn(v.x, v.y);
        p[1] = __floats2half2_rn(v.z, v.w);
    }
    // B tile: Wt[rel] 128x128 halves, 16B vector copies.
    const float4* Wt4 = (const float4*)(g_Wt + (size_t)rel * DFEAT * DFEAT);
#pragma unroll
    for (int it = 0; it < (DFEAT * DFEAT) / (256 * 8); ++it) {
        int idx  = it * 256 + tid;
        int nrow = idx >> 4;
        int koff = (idx & 15) * 8;
        *(float4*)(Bs + nrow * HLD + koff) = Wt4[idx];
    }
    __syncthreads();

    const int wid  = tid >> 5;
    const int lane = tid & 31;
    const int g    = lane >> 2;   // 0..7
    const int c    = lane & 3;    // 0..3
    const int wm   = wid & 3;     // 0..3 : rows wm*32
    const int wn   = wid >> 2;    // 0..1 : cols wn*64

    // ldmatrix per-lane base addresses (byte addresses in shared space).
    // A, x4 covering (mt tile, k halves): mat0=(rb,k0) mat1=(rb+8,k0)
    //                                     mat2=(rb,k0+8) mat3=(rb+8,k0+8)
    const int a_r   = (lane & 7) + ((lane >> 3) & 1) * 8;  // row within 16
    const int a_c   = (lane >> 4) * 8;                     // k offset 0/8
    unsigned aAddr[2];
#pragma unroll
    for (int mt = 0; mt < 2; ++mt) {
        int rb = wm * 32 + mt * 16;
        aAddr[mt] = (unsigned)__cvta_generic_to_shared(As + (rb + a_r) * HLD + a_c);
    }
    // B, x4 covering (2 nt tiles, k halves): mat0=(nb,k0) mat1=(nb,k0+8)
    //                                        mat2=(nb+8,k0) mat3=(nb+8,k0+8)
    const int b_r = (lane & 7) + (lane >> 4) * 8;          // row within 16
    const int b_c = ((lane >> 3) & 1) * 8;                 // k offset 0/8
    unsigned bAddr[4];
#pragma unroll
    for (int ntp = 0; ntp < 4; ++ntp) {
        int nb = wn * 64 + ntp * 16;
        bAddr[ntp] = (unsigned)__cvta_generic_to_shared(Bs + (nb + b_r) * HLD + b_c);
    }

    float acc[2][8][4];
#pragma unroll
    for (int mt = 0; mt < 2; ++mt)
#pragma unroll
        for (int nt = 0; nt < 8; ++nt)
#pragma unroll
            for (int i = 0; i < 4; ++i) acc[mt][nt][i] = 0.f;

#pragma unroll
    for (int k0 = 0; k0 < DFEAT; k0 += 16) {
        unsigned a[2][4], b[8][2];
#pragma unroll
        for (int mt = 0; mt < 2; ++mt)
            ldsm_x4(a[mt][0], a[mt][1], a[mt][2], a[mt][3], aAddr[mt] + k0 * 2);
#pragma unroll
        for (int ntp = 0; ntp < 4; ++ntp)
            ldsm_x4(b[2 * ntp][0], b[2 * ntp][1],
                    b[2 * ntp + 1][0], b[2 * ntp + 1][1], bAddr[ntp] + k0 * 2);
#pragma unroll
        for (int mt = 0; mt < 2; ++mt)
#pragma unroll
            for (int nt = 0; nt < 8; ++nt)
                asm volatile(
                    "mma.sync.aligned.m16n8k16.row.col.f32.f16.f16.f32 "
                    "{%0,%1,%2,%3}, {%4,%5,%6,%7}, {%8,%9}, {%0,%1,%2,%3};"
                    : "+f"(acc[mt][nt][0]), "+f"(acc[mt][nt][1]),
                      "+f"(acc[mt][nt][2]), "+f"(acc[mt][nt][3])
                    : "r"(a[mt][0]), "r"(a[mt][1]), "r"(a[mt][2]), "r"(a[mt][3]),
                      "r"(b[nt][0]), "r"(b[nt][1]));
    }

    __half* Yr = g_Y + (size_t)rel * n_nodes * DFEAT;
#pragma unroll
    for (int mt = 0; mt < 2; ++mt) {
        int r_lo = row0 + wm * 32 + mt * 16 + g;
        int r_hi = r_lo + 8;
#pragma unroll
        for (int nt = 0; nt < 8; ++nt) {
            int col = wn * 64 + nt * 8 + 2 * c;
            if (r_lo < n_nodes)
                *(__half2*)(Yr + (size_t)r_lo * DFEAT + col) =
                    __floats2half2_rn(acc[mt][nt][0], acc[mt][nt][1]);
            if (r_hi < n_nodes)
                *(__half2*)(Yr + (size_t)r_hi * DFEAT + col) =
                    __floats2half2_rn(acc[mt][nt][2], acc[mt][nt][3]);
        }
    }
}

// ---------------------------------------------------------------------------
// CSR build
// ---------------------------------------------------------------------------
__global__ void hist_k(const int* __restrict__ dst, int E)
{
    int e = blockIdx.x * blockDim.x + threadIdx.x;
    if (e < E) atomicAdd(&g_deg[dst[e]], 1);
}

// scan1 consumes AND re-zeroes g_deg (replay-safe).
__global__ void scan1_k(int n)
{
    const int tid  = threadIdx.x;
    const int blk  = blockIdx.x;
    const int base = blk * SCAN_CHUNK + tid * 4;

    int d0 = 0, d1 = 0, d2 = 0, d3 = 0;
    if (base     < n) { d0 = g_deg[base];     g_deg[base]     = 0; }
    if (base + 1 < n) { d1 = g_deg[base + 1]; g_deg[base + 1] = 0; }
    if (base + 2 < n) { d2 = g_deg[base + 2]; g_deg[base + 2] = 0; }
    if (base + 3 < n) { d3 = g_deg[base + 3]; g_deg[base + 3] = 0; }
    int s = d0 + d1 + d2 + d3;

    const int lane = tid & 31, wid = tid >> 5;
    int v = s;
#pragma unroll
    for (int off = 1; off < 32; off <<= 1) {
        int t = __shfl_up_sync(0xffffffffu, v, off);
        if (lane >= off) v += t;
    }
    __shared__ int ws[8];
    if (lane == 31) ws[wid] = v;
    __syncthreads();
    if (tid == 0) {
        int r = 0;
#pragma unroll
        for (int i = 0; i < 8; ++i) { int t = ws[i]; ws[i] = r; r += t; }
    }
    __syncthreads();

    int excl = (v - s) + ws[wid];
    if (tid == 255) g_bsum[blk] = excl + s;

    if (base     < n) g_rowptr[base]     = excl;           excl += d0;
    if (base + 1 < n) g_rowptr[base + 1] = excl;           excl += d1;
    if (base + 2 < n) g_rowptr[base + 2] = excl;           excl += d2;
    if (base + 3 < n) g_rowptr[base + 3] = excl;
}

__global__ void scan2_k(int nb)
{
    const int lane = threadIdx.x;
    int i0 = lane * 2, i1 = lane * 2 + 1;
    int a = (i0 < nb) ? g_bsum[i0] : 0;
    int b = (i1 < nb) ? g_bsum[i1] : 0;
    int s = a + b, v = s;
#pragma unroll
    for (int off = 1; off < 32; off <<= 1) {
        int t = __shfl_up_sync(0xffffffffu, v, off);
        if (lane >= off) v += t;
    }
    int excl = v - s;
    if (i0 < nb) g_bsum[i0] = excl;
    if (i1 < nb) g_bsum[i1] = excl + a;
}

__global__ void scan3_k(int n, int E)
{
    const int tid  = threadIdx.x;
    const int blk  = blockIdx.x;
    const int off  = g_bsum[blk];
    const int base = blk * SCAN_CHUNK + tid * 4;
#pragma unroll
    for (int j = 0; j < 4; ++j) {
        int idx = base + j;
        if (idx < n) {
            int r = g_rowptr[idx] + off;
            g_rowptr[idx] = r;
            g_cursor[idx] = r;
        }
    }
    if (blk == 0 && tid == 0) g_rowptr[n] = E;
}

__global__ void scatter_k(const int* __restrict__ src, const int* __restrict__ dst,
                          const int* __restrict__ et, int E, int n)
{
    int e = blockIdx.x * blockDim.x + threadIdx.x;
    if (e >= E) return;
    int d   = dst[e];
    int pos = atomicAdd(&g_cursor[d], 1);
    g_elist[pos] = ((unsigned)et[e] * (unsigned)n + (unsigned)src[e]) * (unsigned)DFEAT;
}

// ---------------------------------------------------------------------------
// Pull: one warp per node. acc(fp32) = feat[n] + sum of fp16 Y rows.
// ---------------------------------------------------------------------------
__device__ __forceinline__ void acc_half4(float4& acc, uint2 u)
{
    float2 f0 = __half22float2(*(__half2*)&u.x);
    float2 f1 = __half22float2(*(__half2*)&u.y);
    acc.x += f0.x; acc.y += f0.y; acc.z += f1.x; acc.w += f1.y;
}

__global__ void __launch_bounds__(256)
pull_k(const float* __restrict__ feat, float* __restrict__ out, int n)
{
    int gw   = (blockIdx.x * 256 + threadIdx.x) >> 5;
    int lane = threadIdx.x & 31;
    if (gw >= n) return;

    int s = g_rowptr[gw];
    int e = g_rowptr[gw + 1];

    float4 acc = *((const float4*)feat + (size_t)gw * 32 + lane);
    const unsigned lo = (unsigned)lane * 4;

    int i = s;
    for (; i + 8 <= e; i += 8) {
        uint2 u[8];
#pragma unroll
        for (int j = 0; j < 8; ++j) {
            unsigned o = g_elist[i + j];
            u[j] = *(const uint2*)(g_Y + (size_t)o + lo);
        }
#pragma unroll
        for (int j = 0; j < 8; ++j) acc_half4(acc, u[j]);
    }
    for (; i + 2 <= e; i += 2) {
        unsigned o0 = g_elist[i];
        unsigned o1 = g_elist[i + 1];
        uint2 u0 = *(const uint2*)(g_Y + (size_t)o0 + lo);
        uint2 u1 = *(const uint2*)(g_Y + (size_t)o1 + lo);
        acc_half4(acc, u0);
        acc_half4(acc, u1);
    }
    if (i < e) {
        unsigned o = g_elist[i];
        uint2 u = *(const uint2*)(g_Y + (size_t)o + lo);
        acc_half4(acc, u);
    }

    *((float4*)out + (size_t)gw * 32 + lane) = acc;
}

// ---------------------------------------------------------------------------
// Launch. GEMM kept as the 4TH launch (ncu -s5 -c1 captures #4).
// ---------------------------------------------------------------------------
extern "C" void kernel_launch(void* const* d_in, const int* in_sizes, int n_in,
                              void* d_out, int out_size)
{
    const float* feat = (const float*)d_in[0];
    const float* W    = (const float*)d_in[1];
    const int*   et   = (const int*)d_in[2];
    const int*   src  = (const int*)d_in[3];
    const int*   dst  = (const int*)d_in[4];
    float*       out  = (float*)d_out;

    const int n  = in_sizes[0] / DFEAT;                 // 50000
    const int R  = in_sizes[1] / (DFEAT * DFEAT);       // 8
    const int E  = in_sizes[2];                          // 640000
    const int nb = (n + SCAN_CHUNK - 1) / SCAN_CHUNK;    // 49

    const int smem_bytes = 2 * TM * HLD * 2;  // 69,632 B
    cudaFuncSetAttribute(gemm_feat_w,
                         cudaFuncAttributeMaxDynamicSharedMemorySize, smem_bytes);

    dim3 tg(DFEAT / 32, DFEAT / 32, R);
    dim3 gg((n + TM - 1) / TM, R);

    hist_k     <<<(E + 255) / 256, 256>>>(dst, E);       // 1
    transpose_w<<<tg, dim3(32, 8)>>>(W);                 // 2
    scan1_k    <<<nb, 256>>>(n);                         // 3
    gemm_feat_w<<<gg, 256, smem_bytes>>>(feat, n);       // 4  <- ncu capture
    scan2_k    <<<1, 32>>>(nb);                          // 5
    scan3_k    <<<nb, 256>>>(n, E);                      // 6
    scatter_k  <<<(E + 255) / 256, 256>>>(src, dst, et, E, n);  // 7
    pull_k     <<<(n * 32 + 255) / 256, 256>>>(feat, out, n);   // 8
}